// round 2
// baseline (speedup 1.0000x reference)
#include <cuda_runtime.h>
#include <math.h>

#define Bn 4
#define Hn 128
#define Wn 128
#define Cn 512
#define NHn 8
#define Dn 64
#define EPSF 1e-7f

// Scratch (allocation-free rule: __device__ globals)
__device__ float g_Q[(size_t)Bn * Hn * Wn * Cn];   // [B,H,W,C] c = n*64 + dd
__device__ float g_K[(size_t)Bn * Hn * Wn * Cn];
__device__ float g_V[(size_t)Bn * Hn * Wn * Cn];
__device__ float g_XV[(size_t)Bn * NHn * Hn * Wn * Dn]; // [B,nh,H,W,d]

// ---------------------------------------------------------------------------
// Kernel A: QKV projection. out = x[65536x512] @ W[512x512] + b, z selects q/k/v
// 64x64 tile per block, BK=16, 256 threads, 4x4 per thread.
// ---------------------------------------------------------------------------
__global__ __launch_bounds__(256) void proj_kernel(
    const float* __restrict__ x,
    const float* __restrict__ wq, const float* __restrict__ bq,
    const float* __restrict__ wk, const float* __restrict__ bk,
    const float* __restrict__ wv, const float* __restrict__ bv)
{
    const int z = blockIdx.z;
    const float* Wm   = (z == 0) ? wq : (z == 1) ? wk : wv;
    const float* bias = (z == 0) ? bq : (z == 1) ? bk : bv;
    float* Out        = (z == 0) ? g_Q : (z == 1) ? g_K : g_V;

    const int m0 = blockIdx.y * 64;
    const int n0 = blockIdx.x * 64;

    __shared__ float As[16 * 68];  // [k][m], padded stride 68
    __shared__ float Bs[16 * 68];  // [k][n]

    const int tid = threadIdx.x;
    const int tx = tid & 15, ty = tid >> 4;

    const int arow = tid >> 2, ac4 = tid & 3;   // A: 64 rows x 4 float4 (k dir)
    const int brow = tid >> 4, bc4 = tid & 15;  // B: 16 rows x 16 float4 (n dir)

    float acc[4][4] = {};

    for (int k0 = 0; k0 < Cn; k0 += 16) {
        float4 a4 = *(const float4*)&x[(size_t)(m0 + arow) * Cn + k0 + ac4 * 4];
        float4 b4 = *(const float4*)&Wm[(size_t)(k0 + brow) * Cn + n0 + bc4 * 4];
        __syncthreads();
        As[(ac4 * 4 + 0) * 68 + arow] = a4.x;
        As[(ac4 * 4 + 1) * 68 + arow] = a4.y;
        As[(ac4 * 4 + 2) * 68 + arow] = a4.z;
        As[(ac4 * 4 + 3) * 68 + arow] = a4.w;
        *(float4*)&Bs[brow * 68 + bc4 * 4] = b4;
        __syncthreads();
#pragma unroll
        for (int k = 0; k < 16; k++) {
            float4 av = *(float4*)&As[k * 68 + ty * 4];
            float4 bv4 = *(float4*)&Bs[k * 68 + tx * 4];
            float a[4] = {av.x, av.y, av.z, av.w};
            float bb[4] = {bv4.x, bv4.y, bv4.z, bv4.w};
#pragma unroll
            for (int i = 0; i < 4; i++)
#pragma unroll
                for (int j = 0; j < 4; j++)
                    acc[i][j] = fmaf(a[i], bb[j], acc[i][j]);
        }
    }

    float4 bias4 = *(const float4*)&bias[n0 + tx * 4];
#pragma unroll
    for (int i = 0; i < 4; i++) {
        float4 o;
        o.x = acc[i][0] + bias4.x;
        o.y = acc[i][1] + bias4.y;
        o.z = acc[i][2] + bias4.z;
        o.w = acc[i][3] + bias4.w;
        *(float4*)&Out[(size_t)(m0 + ty * 4 + i) * Cn + n0 + tx * 4] = o;
    }
}

// ---------------------------------------------------------------------------
// Shared attention core pieces
// smem layout (floats): Qs[128*68] | Ks[128*68] | Vs[128*68]; Ss[128*132]
// overlaid on Qs/Ks (used only after scores are consumed). Total 104448 B.
// ---------------------------------------------------------------------------
#define TSTRIDE 68
#define SSTRIDE 132
#define SMEM_BYTES ((size_t)(3 * 128 * TSTRIDE) * 4)

__device__ __forceinline__ void attn_scores_softmax(
    float* Qs, float* Ks, float* Ss, int tid)
{
    const int tx = tid & 15, ty = tid >> 4;
    float acc[8][8] = {};
#pragma unroll 4
    for (int kk = 0; kk < Dn; kk++) {
        float a[8], bb[8];
#pragma unroll
        for (int i = 0; i < 8; i++) a[i] = Qs[(ty + 16 * i) * TSTRIDE + kk];
#pragma unroll
        for (int j = 0; j < 8; j++) bb[j] = Ks[(tx + 16 * j) * TSTRIDE + kk];
#pragma unroll
        for (int i = 0; i < 8; i++)
#pragma unroll
            for (int j = 0; j < 8; j++)
                acc[i][j] = fmaf(a[i], bb[j], acc[i][j]);
    }
    __syncthreads();  // everyone done reading Qs/Ks before Ss overlays them
#pragma unroll
    for (int i = 0; i < 8; i++)
#pragma unroll
        for (int j = 0; j < 8; j++) {
            float s = acc[i][j];
            s = fminf(fmaxf(s, -1.0f + EPSF), 1.0f - EPSF) * 0.125f;
            Ss[(ty + 16 * i) * SSTRIDE + (tx + 16 * j)] = s;
        }
    __syncthreads();
    // softmax: 2 threads per row, 64 elems each, shfl-combine
    {
        const int r = tid >> 1, hf = tid & 1;
        float* row = &Ss[r * SSTRIDE + hf * 64];
        float m = -1e30f;
#pragma unroll 4
        for (int g = 0; g < 64; g++) m = fmaxf(m, row[g]);
        m = fmaxf(m, __shfl_xor_sync(0xffffffffu, m, 1));
        float s = 0.0f;
#pragma unroll 4
        for (int g = 0; g < 64; g++) {
            float e = expf(row[g] - m);
            row[g] = e;
            s += e;
        }
        s += __shfl_xor_sync(0xffffffffu, s, 1);
        float inv = 1.0f / s;
#pragma unroll 4
        for (int g = 0; g < 64; g++) {
            float p = row[g] * inv;
            if (isnan(p)) p = EPSF;
            p = fminf(fmaxf(p, EPSF), 1.0f - EPSF);
            row[g] = p;
        }
    }
    __syncthreads();
}

// apply: acc2[8][4] = Ss(128x128) @ Vs(128x64); rows = ty+16i, cols = tx+16j
__device__ __forceinline__ void attn_apply(
    const float* Ss, const float* Vs, float acc2[8][4], int tid)
{
    const int tx = tid & 15, ty = tid >> 4;
#pragma unroll 4
    for (int g = 0; g < 128; g++) {
        float a[8], vv[4];
#pragma unroll
        for (int i = 0; i < 8; i++) a[i] = Ss[(ty + 16 * i) * SSTRIDE + g];
#pragma unroll
        for (int j = 0; j < 4; j++) vv[j] = Vs[g * TSTRIDE + tx + 16 * j];
#pragma unroll
        for (int i = 0; i < 8; i++)
#pragma unroll
            for (int j = 0; j < 4; j++)
                acc2[i][j] = fmaf(a[i], vv[j], acc2[i][j]);
    }
}

// ---------------------------------------------------------------------------
// Kernel B: column (vertical) attention. block = (w, n, b).
// S[h][g] = sum_d Q[b,h,w,n,d]*K[b,g,w,n,d]; xv[b,n,h,w,:] = softmax(S) @ Vcol
// ---------------------------------------------------------------------------
__global__ __launch_bounds__(256) void col_attn_kernel()
{
    const int w = blockIdx.x, n = blockIdx.y, b = blockIdx.z;
    extern __shared__ float sm[];
    float* Qs = sm;
    float* Ks = sm + 128 * TSTRIDE;
    float* Vs = sm + 2 * 128 * TSTRIDE;
    float* Ss = sm;  // overlays Qs/Ks after score phase

    const int tid = threadIdx.x;
    const size_t base = (size_t)b * Hn * Wn * Cn + (size_t)w * Cn + n * Dn;

#pragma unroll
    for (int i = 0; i < 8; i++) {
        int idx = tid + i * 256;
        int h = idx >> 4, c4 = idx & 15;
        size_t off = base + (size_t)h * Wn * Cn + c4 * 4;
        *(float4*)&Qs[h * TSTRIDE + c4 * 4] = *(const float4*)&g_Q[off];
        *(float4*)&Ks[h * TSTRIDE + c4 * 4] = *(const float4*)&g_K[off];
        *(float4*)&Vs[h * TSTRIDE + c4 * 4] = *(const float4*)&g_V[off];
    }
    __syncthreads();

    attn_scores_softmax(Qs, Ks, Ss, tid);

    float acc2[8][4] = {};
    attn_apply(Ss, Vs, acc2, tid);

    const int tx = tid & 15, ty = tid >> 4;
#pragma unroll
    for (int i = 0; i < 8; i++) {
        int h = ty + 16 * i;
        size_t ob = ((((size_t)b * NHn + n) * Hn + h) * Wn + w) * Dn;
#pragma unroll
        for (int j = 0; j < 4; j++)
            g_XV[ob + tx + 16 * j] = acc2[i][j];
    }
}

// ---------------------------------------------------------------------------
// Kernel C: row (horizontal) attention. block = (h, n, b).
// U[w][v] = sum_d Q[b,h,w,n,d]*K[b,h,v,n,d]; out = softmax(U) @ xv_row,
// channel order c = dd*8 + n.
// ---------------------------------------------------------------------------
__global__ __launch_bounds__(256) void row_attn_kernel(float* __restrict__ out)
{
    const int h = blockIdx.x, n = blockIdx.y, b = blockIdx.z;
    extern __shared__ float sm[];
    float* Qs = sm;
    float* Ks = sm + 128 * TSTRIDE;
    float* Vs = sm + 2 * 128 * TSTRIDE;
    float* Ss = sm;

    const int tid = threadIdx.x;
    const size_t base = ((size_t)b * Hn + h) * Wn * Cn + n * Dn;
    const size_t xvbase = (((size_t)b * NHn + n) * Hn + h) * (size_t)(Wn * Dn);

#pragma unroll
    for (int i = 0; i < 8; i++) {
        int idx = tid + i * 256;
        int w = idx >> 4, c4 = idx & 15;
        size_t off = base + (size_t)w * Cn + c4 * 4;
        *(float4*)&Qs[w * TSTRIDE + c4 * 4] = *(const float4*)&g_Q[off];
        *(float4*)&Ks[w * TSTRIDE + c4 * 4] = *(const float4*)&g_K[off];
        *(float4*)&Vs[w * TSTRIDE + c4 * 4] = *(const float4*)&g_XV[xvbase + idx * 4];
    }
    __syncthreads();

    attn_scores_softmax(Qs, Ks, Ss, tid);

    float acc2[8][4] = {};
    attn_apply(Ss, Vs, acc2, tid);

    const int tx = tid & 15, ty = tid >> 4;
#pragma unroll
    for (int i = 0; i < 8; i++) {
        int w = ty + 16 * i;
        size_t ob = (((size_t)b * Hn + h) * Wn + w) * Cn + n;
#pragma unroll
        for (int j = 0; j < 4; j++) {
            int dd = tx + 16 * j;
            out[ob + (size_t)dd * NHn] = acc2[i][j];
        }
    }
}

// ---------------------------------------------------------------------------
extern "C" void kernel_launch(void* const* d_in, const int* in_sizes, int n_in,
                              void* d_out, int out_size)
{
    const float* x  = (const float*)d_in[0];
    const float* wq = (const float*)d_in[1];
    const float* bq = (const float*)d_in[2];
    const float* wk = (const float*)d_in[3];
    const float* bk = (const float*)d_in[4];
    const float* wv = (const float*)d_in[5];
    const float* bv = (const float*)d_in[6];
    float* out = (float*)d_out;

    (void)in_sizes; (void)n_in; (void)out_size;

    // Projection: grid (N/64, M/64, 3)
    proj_kernel<<<dim3(Cn / 64, (Bn * Hn * Wn) / 64, 3), 256>>>(
        x, wq, bq, wk, bk, wv, bv);

    cudaFuncSetAttribute(col_attn_kernel,
                         cudaFuncAttributeMaxDynamicSharedMemorySize,
                         (int)SMEM_BYTES);
    cudaFuncSetAttribute(row_attn_kernel,
                         cudaFuncAttributeMaxDynamicSharedMemorySize,
                         (int)SMEM_BYTES);

    col_attn_kernel<<<dim3(Wn, NHn, Bn), 256, SMEM_BYTES>>>();
    row_attn_kernel<<<dim3(Hn, NHn, Bn), 256, SMEM_BYTES>>>(out);
}

// round 10
// speedup vs baseline: 1.6577x; 1.6577x over previous
#include <cuda_runtime.h>
#include <cuda_bf16.h>
#include <math.h>
#include <stdint.h>

#define Bn 4
#define Hn 128
#define Wn 128
#define Cn 512
#define NHn 8
#define Dn 64
#define EPSF 1e-7f

#define Mtot (Bn * Hn * Wn)      // 65536 rows

// ---------------- device scratch (allocation-free rule) ----------------
__device__ float g_Q[(size_t)Mtot * Cn];
__device__ float g_K[(size_t)Mtot * Cn];
__device__ float g_V[(size_t)Mtot * Cn];
__device__ float g_XV[(size_t)Bn * NHn * Hn * Wn * Dn];

__device__ __nv_bfloat16 g_xhi[(size_t)Mtot * Cn];
__device__ __nv_bfloat16 g_xlo[(size_t)Mtot * Cn];
__device__ __nv_bfloat16 g_whiT[3 * Cn * Cn];   // [z][n][k] = w_z[k][n] hi
__device__ __nv_bfloat16 g_wloT[3 * Cn * Cn];   // lo part

// ---------------- PTX helpers ----------------
__device__ __forceinline__ uint32_t smem_u32(const void* p) {
    uint32_t a;
    asm("{ .reg .u64 t; cvta.to.shared.u64 t, %1; cvt.u32.u64 %0, t; }"
        : "=r"(a) : "l"(p));
    return a;
}
__device__ __forceinline__ void cp_async16(uint32_t dst, const void* src) {
    asm volatile("cp.async.cg.shared.global [%0], [%1], 16;\n"
                 :: "r"(dst), "l"(__cvta_generic_to_global(src)) : "memory");
}
__device__ __forceinline__ void cp_commit() {
    asm volatile("cp.async.commit_group;\n" ::: "memory");
}
__device__ __forceinline__ void cp_wait0() {
    asm volatile("cp.async.wait_group 0;\n" ::: "memory");
}
__device__ __forceinline__ void ldsm_x4(uint32_t* r, uint32_t addr) {
    asm volatile("ldmatrix.sync.aligned.m8n8.x4.shared.b16 {%0,%1,%2,%3}, [%4];"
                 : "=r"(r[0]), "=r"(r[1]), "=r"(r[2]), "=r"(r[3]) : "r"(addr));
}
__device__ __forceinline__ void ldsm_x2(uint32_t* r, uint32_t addr) {
    asm volatile("ldmatrix.sync.aligned.m8n8.x2.shared.b16 {%0,%1}, [%2];"
                 : "=r"(r[0]), "=r"(r[1]) : "r"(addr));
}
__device__ __forceinline__ void mma_bf16(float* c, const uint32_t* a, const uint32_t* b) {
    asm volatile(
        "mma.sync.aligned.m16n8k16.row.col.f32.bf16.bf16.f32 "
        "{%0,%1,%2,%3}, {%4,%5,%6,%7}, {%8,%9}, {%0,%1,%2,%3};"
        : "+f"(c[0]), "+f"(c[1]), "+f"(c[2]), "+f"(c[3])
        : "r"(a[0]), "r"(a[1]), "r"(a[2]), "r"(a[3]), "r"(b[0]), "r"(b[1]));
}

// ---------------- prep: split x into bf16 hi/lo ----------------
__global__ __launch_bounds__(256) void split_x_kernel(const float* __restrict__ x)
{
    size_t i4 = ((size_t)blockIdx.x * 256 + threadIdx.x);
    size_t stride = (size_t)gridDim.x * 256;
    size_t n4 = (size_t)Mtot * Cn / 4;
    for (; i4 < n4; i4 += stride) {
        float4 v = *(const float4*)&((const float4*)x)[i4];
        __nv_bfloat16 h[4], l[4];
        float vv[4] = {v.x, v.y, v.z, v.w};
#pragma unroll
        for (int j = 0; j < 4; j++) {
            h[j] = __float2bfloat16(vv[j]);
            l[j] = __float2bfloat16(vv[j] - __bfloat162float(h[j]));
        }
        *(uint2*)&g_xhi[i4 * 4] = *(uint2*)h;
        *(uint2*)&g_xlo[i4 * 4] = *(uint2*)l;
    }
}

// ---------------- prep: transpose + split weights ----------------
__global__ __launch_bounds__(256) void split_w_kernel(
    const float* __restrict__ wq, const float* __restrict__ wk,
    const float* __restrict__ wv)
{
    const int z = blockIdx.z;
    const float* src = (z == 0) ? wq : (z == 1) ? wk : wv;
    __shared__ float t[32][33];
    const int k0 = blockIdx.x * 32, n0 = blockIdx.y * 32;
    const int tx = threadIdx.x & 31, ty = threadIdx.x >> 5;  // 32 x 8
#pragma unroll
    for (int i = 0; i < 4; i++)
        t[ty + 8 * i][tx] = src[(size_t)(k0 + ty + 8 * i) * Cn + n0 + tx];
    __syncthreads();
#pragma unroll
    for (int i = 0; i < 4; i++) {
        float v = t[tx][ty + 8 * i];
        __nv_bfloat16 h = __float2bfloat16(v);
        __nv_bfloat16 l = __float2bfloat16(v - __bfloat162float(h));
        size_t o = (size_t)z * Cn * Cn + (size_t)(n0 + ty + 8 * i) * Cn + k0 + tx;
        g_whiT[o] = h;
        g_wloT[o] = l;
    }
}

// ---------------- HMMA split-bf16 projection GEMM ----------------
// grid (4, 512, 3): x = N-tile (128 cols), y = M-tile (128 rows), z = q/k/v
// D[128x128] = A'[128 x 1536] @ B'^T, A'=[xhi|xlo|xhi], B'=[whi|whi|wlo]
// 8 warps in 2(m) x 4(n): each warp 64x32. BK=32, double-buffered cp.async.
#define PK 1536
#define PBK 32
#define PITERS (PK / PBK)          // 48
#define PSTRIDE 40                 // bf16 elems per smem row (32 + 8 pad)
#define PTILE_B (128 * PSTRIDE * 2)   // 10240 bytes per operand tile
#define PSTAGE_B (2 * PTILE_B)        // 20480 per stage

__global__ __launch_bounds__(256) void proj_hmma_kernel(
    const float* __restrict__ bq, const float* __restrict__ bk,
    const float* __restrict__ bv)
{
    __shared__ __align__(16) char psm[2 * PSTAGE_B];   // 40960 B

    const int tid = threadIdx.x;
    const int wid = tid >> 5, lane = tid & 31;
    const int z = blockIdx.z;
    const int m0 = blockIdx.y * 128;
    const int n0c = blockIdx.x * 128;
    const float* bias = (z == 0) ? bq : (z == 1) ? bk : bv;
    float* Out        = (z == 0) ? g_Q : (z == 1) ? g_K : g_V;

    const __nv_bfloat16* whiT = g_whiT + (size_t)z * Cn * Cn;
    const __nv_bfloat16* wloT = g_wloT + (size_t)z * Cn * Cn;

    const uint32_t smem = smem_u32(psm);

    const int warp_m = (wid >> 2) * 64;   // 0 or 64
    const int warp_n = (wid & 3) * 32;    // 0,32,64,96

    // ldmatrix per-thread byte offsets (within a stage's A / B tile)
    const int ml = lane & 15, kcA = (lane >> 4) * 8;
    uint32_t a_off[4];
#pragma unroll
    for (int mi = 0; mi < 4; mi++)
        a_off[mi] = ((warp_m + 16 * mi + ml) * PSTRIDE + kcA) * 2;
    const int nl = lane & 7, kcB = ((lane >> 3) & 1) * 8;
    uint32_t b_off[4];
#pragma unroll
    for (int ni = 0; ni < 4; ni++)
        b_off[ni] = ((warp_n + 8 * ni + nl) * PSTRIDE + kcB) * 2;

    // stage loader: A 512 chunks + B 512 chunks of 16B, 4 per thread
    auto load_stage = [&](int it, int buf) {
        const int reg = it >> 4;                 // 0,1,2
        const int klocal = (it & 15) * PBK;      // 0..480
        const __nv_bfloat16* xs = (reg == 1) ? g_xlo : g_xhi;
        const __nv_bfloat16* ws = (reg == 2) ? wloT : whiT;
        const uint32_t sb = smem + buf * PSTAGE_B;
#pragma unroll
        for (int i = 0; i < 4; i++) {
            int u = tid + i * 256;
            int isB = u >> 9;                    // 0: A, 1: B
            int v = u & 511;
            int row = v >> 2, chunk = v & 3;
            uint32_t dst = sb + isB * PTILE_B + row * (PSTRIDE * 2) + chunk * 16;
            const __nv_bfloat16* src = isB
                ? ws + ((size_t)(n0c + row) * Cn + klocal + chunk * 8)
                : xs + ((size_t)(m0 + row) * Cn + klocal + chunk * 8);
            cp_async16(dst, src);
        }
        cp_commit();
    };

    float acc[4][4][4];
#pragma unroll
    for (int mi = 0; mi < 4; mi++)
#pragma unroll
        for (int ni = 0; ni < 4; ni++)
#pragma unroll
            for (int q = 0; q < 4; q++) acc[mi][ni][q] = 0.0f;

    load_stage(0, 0);
    cp_wait0();
    __syncthreads();

#pragma unroll 1
    for (int it = 0; it < PITERS; it++) {
        const int buf = it & 1;
        if (it + 1 < PITERS) load_stage(it + 1, buf ^ 1);

        const uint32_t As = smem + buf * PSTAGE_B;
        const uint32_t Bs = As + PTILE_B;
#pragma unroll
        for (int kh = 0; kh < 2; kh++) {
            const uint32_t kb = (kh * 16) * 2;   // byte offset of k16 step
            uint32_t af[4][4], bf[4][2];
#pragma unroll
            for (int mi = 0; mi < 4; mi++) ldsm_x4(af[mi], As + a_off[mi] + kb);
#pragma unroll
            for (int ni = 0; ni < 4; ni++) ldsm_x2(bf[ni], Bs + b_off[ni] + kb);
#pragma unroll
            for (int mi = 0; mi < 4; mi++)
#pragma unroll
                for (int ni = 0; ni < 4; ni++)
                    mma_bf16(acc[mi][ni], af[mi], bf[ni]);
        }

        if (it + 1 < PITERS) cp_wait0();
        __syncthreads();
    }

    // epilogue: d0,d1 -> (m, n..n+1), d2,d3 -> (m+8, n..n+1)
    const int rbase = m0 + warp_m + (lane >> 2);
    const int cbase = n0c + warp_n + 2 * (lane & 3);
#pragma unroll
    for (int mi = 0; mi < 4; mi++) {
#pragma unroll
        for (int ni = 0; ni < 4; ni++) {
            int col = cbase + 8 * ni;
            float2 b2 = *(const float2*)&bias[col];
            int r0 = rbase + 16 * mi;
            float2 v0 = {acc[mi][ni][0] + b2.x, acc[mi][ni][1] + b2.y};
            float2 v1 = {acc[mi][ni][2] + b2.x, acc[mi][ni][3] + b2.y};
            *(float2*)&Out[(size_t)r0 * Cn + col] = v0;
            *(float2*)&Out[(size_t)(r0 + 8) * Cn + col] = v1;
        }
    }
}

// ---------------------------------------------------------------------------
// Attention (unchanged from validated round-2 kernel)
// ---------------------------------------------------------------------------
#define TSTRIDE 68
#define SSTRIDE 132
#define SMEM_BYTES ((size_t)(3 * 128 * TSTRIDE) * 4)

__device__ __forceinline__ void attn_scores_softmax(
    float* Qs, float* Ks, float* Ss, int tid)
{
    const int tx = tid & 15, ty = tid >> 4;
    float acc[8][8] = {};
#pragma unroll 4
    for (int kk = 0; kk < Dn; kk++) {
        float a[8], bb[8];
#pragma unroll
        for (int i = 0; i < 8; i++) a[i] = Qs[(ty + 16 * i) * TSTRIDE + kk];
#pragma unroll
        for (int j = 0; j < 8; j++) bb[j] = Ks[(tx + 16 * j) * TSTRIDE + kk];
#pragma unroll
        for (int i = 0; i < 8; i++)
#pragma unroll
            for (int j = 0; j < 8; j++)
                acc[i][j] = fmaf(a[i], bb[j], acc[i][j]);
    }
    __syncthreads();
#pragma unroll
    for (int i = 0; i < 8; i++)
#pragma unroll
        for (int j = 0; j < 8; j++) {
            float s = acc[i][j];
            s = fminf(fmaxf(s, -1.0f + EPSF), 1.0f - EPSF) * 0.125f;
            Ss[(ty + 16 * i) * SSTRIDE + (tx + 16 * j)] = s;
        }
    __syncthreads();
    {
        const int r = tid >> 1, hf = tid & 1;
        float* row = &Ss[r * SSTRIDE + hf * 64];
        float m = -1e30f;
#pragma unroll 4
        for (int g = 0; g < 64; g++) m = fmaxf(m, row[g]);
        m = fmaxf(m, __shfl_xor_sync(0xffffffffu, m, 1));
        float s = 0.0f;
#pragma unroll 4
        for (int g = 0; g < 64; g++) {
            float e = expf(row[g] - m);
            row[g] = e;
            s += e;
        }
        s += __shfl_xor_sync(0xffffffffu, s, 1);
        float inv = 1.0f / s;
#pragma unroll 4
        for (int g = 0; g < 64; g++) {
            float p = row[g] * inv;
            if (isnan(p)) p = EPSF;
            p = fminf(fmaxf(p, EPSF), 1.0f - EPSF);
            row[g] = p;
        }
    }
    __syncthreads();
}

__device__ __forceinline__ void attn_apply(
    const float* Ss, const float* Vs, float acc2[8][4], int tid)
{
    const int tx = tid & 15, ty = tid >> 4;
#pragma unroll 4
    for (int g = 0; g < 128; g++) {
        float a[8], vv[4];
#pragma unroll
        for (int i = 0; i < 8; i++) a[i] = Ss[(ty + 16 * i) * SSTRIDE + g];
#pragma unroll
        for (int j = 0; j < 4; j++) vv[j] = Vs[g * TSTRIDE + tx + 16 * j];
#pragma unroll
        for (int i = 0; i < 8; i++)
#pragma unroll
            for (int j = 0; j < 4; j++)
                acc2[i][j] = fmaf(a[i], vv[j], acc2[i][j]);
    }
}

__global__ __launch_bounds__(256) void col_attn_kernel()
{
    const int w = blockIdx.x, n = blockIdx.y, b = blockIdx.z;
    extern __shared__ float sm[];
    float* Qs = sm;
    float* Ks = sm + 128 * TSTRIDE;
    float* Vs = sm + 2 * 128 * TSTRIDE;
    float* Ss = sm;

    const int tid = threadIdx.x;
    const size_t base = (size_t)b * Hn * Wn * Cn + (size_t)w * Cn + n * Dn;

#pragma unroll
    for (int i = 0; i < 8; i++) {
        int idx = tid + i * 256;
        int h = idx >> 4, c4 = idx & 15;
        size_t off = base + (size_t)h * Wn * Cn + c4 * 4;
        *(float4*)&Qs[h * TSTRIDE + c4 * 4] = *(const float4*)&g_Q[off];
        *(float4*)&Ks[h * TSTRIDE + c4 * 4] = *(const float4*)&g_K[off];
        *(float4*)&Vs[h * TSTRIDE + c4 * 4] = *(const float4*)&g_V[off];
    }
    __syncthreads();

    attn_scores_softmax(Qs, Ks, Ss, tid);

    float acc2[8][4] = {};
    attn_apply(Ss, Vs, acc2, tid);

    const int tx = tid & 15, ty = tid >> 4;
#pragma unroll
    for (int i = 0; i < 8; i++) {
        int h = ty + 16 * i;
        size_t ob = ((((size_t)b * NHn + n) * Hn + h) * Wn + w) * Dn;
#pragma unroll
        for (int j = 0; j < 4; j++)
            g_XV[ob + tx + 16 * j] = acc2[i][j];
    }
}

__global__ __launch_bounds__(256) void row_attn_kernel(float* __restrict__ out)
{
    const int h = blockIdx.x, n = blockIdx.y, b = blockIdx.z;
    extern __shared__ float sm[];
    float* Qs = sm;
    float* Ks = sm + 128 * TSTRIDE;
    float* Vs = sm + 2 * 128 * TSTRIDE;
    float* Ss = sm;

    const int tid = threadIdx.x;
    const size_t base = ((size_t)b * Hn + h) * Wn * Cn + n * Dn;
    const size_t xvbase = (((size_t)b * NHn + n) * Hn + h) * (size_t)(Wn * Dn);

#pragma unroll
    for (int i = 0; i < 8; i++) {
        int idx = tid + i * 256;
        int w = idx >> 4, c4 = idx & 15;
        size_t off = base + (size_t)w * Cn + c4 * 4;
        *(float4*)&Qs[w * TSTRIDE + c4 * 4] = *(const float4*)&g_Q[off];
        *(float4*)&Ks[w * TSTRIDE + c4 * 4] = *(const float4*)&g_K[off];
        *(float4*)&Vs[w * TSTRIDE + c4 * 4] = *(const float4*)&g_XV[xvbase + idx * 4];
    }
    __syncthreads();

    attn_scores_softmax(Qs, Ks, Ss, tid);

    float acc2[8][4] = {};
    attn_apply(Ss, Vs, acc2, tid);

    const int tx = tid & 15, ty = tid >> 4;
#pragma unroll
    for (int i = 0; i < 8; i++) {
        int w = ty + 16 * i;
        size_t ob = (((size_t)b * Hn + h) * Wn + w) * Cn + n;
#pragma unroll
        for (int j = 0; j < 4; j++) {
            int dd = tx + 16 * j;
            out[ob + (size_t)dd * NHn] = acc2[i][j];
        }
    }
}

// ---------------------------------------------------------------------------
extern "C" void kernel_launch(void* const* d_in, const int* in_sizes, int n_in,
                              void* d_out, int out_size)
{
    const float* x  = (const float*)d_in[0];
    const float* wq = (const float*)d_in[1];
    const float* bq = (const float*)d_in[2];
    const float* wk = (const float*)d_in[3];
    const float* bk = (const float*)d_in[4];
    const float* wv = (const float*)d_in[5];
    const float* bv = (const float*)d_in[6];
    float* out = (float*)d_out;

    (void)in_sizes; (void)n_in; (void)out_size;

    split_x_kernel<<<8192, 256>>>(x);
    split_w_kernel<<<dim3(16, 16, 3), 256>>>(wq, wk, wv);

    proj_hmma_kernel<<<dim3(4, 512, 3), 256>>>(bq, bk, bv);

    cudaFuncSetAttribute(col_attn_kernel,
                         cudaFuncAttributeMaxDynamicSharedMemorySize,
                         (int)SMEM_BYTES);
    cudaFuncSetAttribute(row_attn_kernel,
                         cudaFuncAttributeMaxDynamicSharedMemorySize,
                         (int)SMEM_BYTES);

    col_attn_kernel<<<dim3(Wn, NHn, Bn), 256, SMEM_BYTES>>>();
    row_attn_kernel<<<dim3(Hn, NHn, Bn), 256, SMEM_BYTES>>>(out);
}